// round 17
// baseline (speedup 1.0000x reference)
#include <cuda_runtime.h>

#define BB   1024
#define CC   3
#define PROW 4
#define PCOL 5
#define PP   20      // PROW*PCOL
#define HID  32
#define HH   224
#define WW   220
#define PH   56      // HH/PROW
#define PW   44      // WW/PCOL
#define W4   55      // WW/4 float4 per row
#define PW4  11      // PW/4 float4 per column-patch

// per-(image, patch, channel) partial sums + fan-in counters
__device__ float        g_scratch[BB * PP * CC];
__device__ unsigned int g_cnt[BB];      // zero-init; atom.inc wraps -> replayable

// ---------------------------------------------------------------------------
// Single kernel: grid = (BB, CC), block = (56, 8). Pool phase byte-identical
// to the proven 6.9 TB/s config (__ldcs streaming float4). Fan-in uses ONE
// atom.acq_rel.gpu.inc per block — release publishes this block's scratch
// writes, acquire (on the last arriver) orders its reads. No MEMBAR.GPU, no
// CCTL.IVALL in the stream (the R5 mistake). Last channel-block per image
// runs the 20-patch MLP + score, overlapped with other blocks' streaming.
// ---------------------------------------------------------------------------
__global__ __launch_bounds__(448)
void nam_fused_kernel(const float* __restrict__ x,
                      const float* __restrict__ w1,
                      const float* __restrict__ b1,
                      const float* __restrict__ w2,
                      const float* __restrict__ b2,
                      float* __restrict__ out)
{
    const int b  = blockIdx.x;
    const int c  = blockIdx.y;
    const int tx = threadIdx.x;   // 0..55 (55 idle for loads)
    const int ty = threadIdx.y;   // 0..7

    const float4* base = (const float4*)(x) + (size_t)(b * CC + c) * (HH * W4);

    float acc[PROW] = {0.f, 0.f, 0.f, 0.f};

    if (tx < W4) {
        #pragma unroll
        for (int pr = 0; pr < PROW; pr++) {
            #pragma unroll
            for (int i = 0; i < PH / 8; i++) {          // 7 row-groups
                const int h = pr * PH + i * 8 + ty;
                float4 v = __ldcs(&base[h * W4 + tx]);
                acc[pr] += (v.x + v.y) + (v.z + v.w);
            }
        }
    }

    __shared__ float part[PROW][8][56];
    #pragma unroll
    for (int pr = 0; pr < PROW; pr++)
        part[pr][ty][tx] = acc[pr];                      // tx==55 stores 0
    __syncthreads();

    const int tid = ty * 56 + tx;
    if (tid < PP) {
        const int pr = tid / PCOL;
        const int pc = tid % PCOL;
        float s = 0.f;
        #pragma unroll
        for (int yy = 0; yy < 8; yy++) {
            float a = 0.f;
            #pragma unroll
            for (int k = 0; k < PW4; k++)
                a += part[pr][yy][pc * PW4 + k];
            s += a;
        }
        g_scratch[(b * PP + tid) * CC + c] = s;
    }
    __syncthreads();                                     // scratch writes done

    // Fan-in: one acq_rel inc per block; wraps at CC-1 (graph-replayable).
    __shared__ unsigned int s_last;
    if (tid == 0) {
        unsigned int old;
        asm volatile("atom.acq_rel.gpu.global.inc.u32 %0, [%1], %2;"
                     : "=r"(old)
                     : "l"(&g_cnt[b]), "r"((unsigned)(CC - 1))
                     : "memory");
        s_last = (old == CC - 1) ? 1u : 0u;
    }
    __syncthreads();

    if (s_last && tid < 32) {
        float o = 0.f;
        if (tid < PP) {
            const float* sp = &g_scratch[(b * PP + tid) * CC];
            const float f = (__ldcg(&sp[0]) + __ldcg(&sp[1]) + __ldcg(&sp[2]))
                            * (1.0f / (CC * PH * PW));
            o = b2[tid];
            const float* w1p = w1 + tid * HID;
            const float* b1p = b1 + tid * HID;
            const float* w2p = w2 + tid * HID;
            #pragma unroll
            for (int k = 0; k < HID; k++) {
                float h = fmaf(f, w1p[k], b1p[k]);
                h = fmaxf(h, 0.0f);
                o = fmaf(h, w2p[k], o);
            }
            out[BB + b * PP + tid] = o;                  // contribs section
        }
        float sc = o;                                    // lanes >= 20 add 0
        #pragma unroll
        for (int off = 16; off > 0; off >>= 1)
            sc += __shfl_down_sync(0xFFFFFFFFu, sc, off);
        if (tid == 0)
            out[b] = sc;                                 // score section
    }
}

extern "C" void kernel_launch(void* const* d_in, const int* in_sizes, int n_in,
                              void* d_out, int out_size)
{
    const float* x  = (const float*)d_in[0];
    const float* w1 = (const float*)d_in[1];
    const float* b1 = (const float*)d_in[2];
    const float* w2 = (const float*)d_in[3];
    const float* b2 = (const float*)d_in[4];
    float* out = (float*)d_out;

    nam_fused_kernel<<<dim3(BB, CC), dim3(56, 8)>>>(x, w1, b1, w2, b2, out);
}